// round 2
// baseline (speedup 1.0000x reference)
#include <cuda_runtime.h>

// 4-qubit depth-2 variational circuit, B=2^20 samples.
//
// Reformulation: for real product state psi (rank-1 over qubits),
//   z_w = psi^T A_w psi,   A_w = Re(U^H Z_w U)  (16x16 real symmetric)
// and per qubit  v[b]*v[b'] = (1/2)(e0*1 + e1*cos(x*pi) + e2*sin(x*pi)),
// so  z_w = sum_{k,l in [0,9)} T4[k*9+l].w * r01[k] * r23[l]
// with r01 = outer((1,C0,S0),(1,C1,S1)), r23 = outer((1,C2,S2),(1,C3,S3)).
// T4 (81 float4, one component per wire) is batch-independent -> prep kernel.
// Main kernel: 2 samples/thread, all math packed with fma.rn.f32x2.

__device__ float4 g_T4[81];

// ---------------- packed f32x2 helpers ----------------
#define PACKX2(d, lo, hi) \
    asm("mov.b64 %0, {%1, %2};" : "=l"(d) : "f"(lo), "f"(hi))
#define UNPACKX2(lo, hi, s) \
    asm("mov.b64 {%0, %1}, %2;" : "=f"(lo), "=f"(hi) : "l"(s))
#define MULX2(d, a, b) \
    asm("mul.rn.f32x2 %0, %1, %2;" : "=l"(d) : "l"(a), "l"(b))
#define FMAX2(d, a, b, c) \
    asm("fma.rn.f32x2 %0, %1, %2, %3;" : "=l"(d) : "l"(a), "l"(b), "l"(c))

// ---------------- prep: build T4 from weights ----------------
__global__ void qc_prep_kernel(const float* __restrict__ w) {
    __shared__ float sUr[16][16], sUi[16][16];   // U[s][j]
    __shared__ float sA[4][16][16];              // A_w[j][jp]
    int tid = threadIdx.x;

    // Stage 1: 16 threads each evolve one basis column |j>
    if (tid < 16) {
        int j = tid;
        float re[16], im[16];
#pragma unroll
        for (int s = 0; s < 16; ++s) { re[s] = (s == j) ? 1.0f : 0.0f; im[s] = 0.0f; }
        const int ctrl[4] = {0, 1, 2, 3};
        const int targ[4] = {1, 2, 3, 0};
        for (int d = 0; d < 2; ++d) {
            for (int g = 0; g < 4; ++g) {
                int cm = 8 >> ctrl[g], tm = 8 >> targ[g];
                float tre[16], tim[16];
                for (int s = 0; s < 16; ++s) {
                    int src = (s & cm) ? (s ^ tm) : s;
                    tre[s] = re[src]; tim[s] = im[src];
                }
                for (int s = 0; s < 16; ++s) { re[s] = tre[s]; im[s] = tim[s]; }
            }
            for (int q = 0; q < 4; ++q) {
                int m = 8 >> q;
                float th = w[d * 8 + q * 2 + 0];
                float cy, sy; sincosf(0.5f * th, &sy, &cy);
                for (int s = 0; s < 16; ++s) {
                    if (s & m) continue;
                    int s1 = s | m;
                    float r0 = re[s], i0 = im[s], r1 = re[s1], i1 = im[s1];
                    re[s]  = cy * r0 - sy * r1;  im[s]  = cy * i0 - sy * i1;
                    re[s1] = sy * r0 + cy * r1;  im[s1] = sy * i0 + cy * i1;
                }
                float ph = w[d * 8 + q * 2 + 1];
                float cp, sp; sincosf(0.5f * ph, &sp, &cp);
                for (int s = 0; s < 16; ++s) {
                    float r = re[s], i = im[s];
                    if (s & m) { re[s] = r * cp - i * sp;  im[s] = i * cp + r * sp; }
                    else       { re[s] = r * cp + i * sp;  im[s] = i * cp - r * sp; }
                }
            }
        }
#pragma unroll
        for (int s = 0; s < 16; ++s) { sUr[s][j] = re[s]; sUi[s][j] = im[s]; }
    }
    __syncthreads();

    // Stage 2: A_w[j][jp] = sum_s sign_w(s) * (Ur[s][j]Ur[s][jp] + Ui[s][j]Ui[s][jp])
    for (int e = tid; e < 1024; e += blockDim.x) {
        int wq = e >> 8;          // wire 0..3
        int j  = (e >> 4) & 15;
        int jp = e & 15;
        int mask = 8 >> wq;
        float acc = 0.f;
        for (int s = 0; s < 16; ++s) {
            float v = sUr[s][j] * sUr[s][jp] + sUi[s][j] * sUi[s][jp];
            acc += (s & mask) ? -v : v;
        }
        sA[wq][j][jp] = acc;
    }
    __syncthreads();

    // Stage 3: T4[k*9+l].w = (1/16) * sum_{j,jp} A_w[j][jp] * prod_q Mfac
    //   Mfac(b,bp,i): i<2 requires b==bp, value (i==0)?1:(b?-1:1);
    //                 i==2 requires b!=bp, value 1.
    if (tid < 81) {
        int k = tid / 9, l = tid % 9;
        int iq[4] = {k / 3, k % 3, l / 3, l % 3};
        float t0 = 0.f, t1 = 0.f, t2 = 0.f, t3 = 0.f;
        for (int j = 0; j < 16; ++j) {
            for (int jp = 0; jp < 16; ++jp) {
                int wgt = 1;
                for (int q = 0; q < 4 && wgt; ++q) {
                    int b  = (j  >> (3 - q)) & 1;
                    int bp = (jp >> (3 - q)) & 1;
                    int i  = iq[q];
                    if (i == 2)      wgt = (b != bp) ? wgt : 0;
                    else if (b != bp) wgt = 0;
                    else if (i == 1 && b) wgt = -wgt;
                }
                if (wgt) {
                    float fw = (float)wgt;
                    t0 += fw * sA[0][j][jp];
                    t1 += fw * sA[1][j][jp];
                    t2 += fw * sA[2][j][jp];
                    t3 += fw * sA[3][j][jp];
                }
            }
        }
        const float inv16 = 1.0f / 16.0f;
        g_T4[tid] = make_float4(t0 * inv16, t1 * inv16, t2 * inv16, t3 * inv16);
    }
}

// ---------------- main: 2 samples per thread, f32x2 packed ----------------
__global__ void __launch_bounds__(256) qc_main_kernel(
    const float4* __restrict__ x, float4* __restrict__ out, int halfB) {
    __shared__ float4 Ts[81];
    int tid = threadIdx.x;
    if (tid < 81) Ts[tid] = g_T4[tid];
    __syncthreads();

    int t = blockIdx.x * 256 + tid;
    if (t >= halfB) return;

    const float PI_F = 3.14159265358979323846f;
    float4 xa = x[t];
    float4 xb = x[t + halfB];

    float C0a, S0a, C1a, S1a, C2a, S2a, C3a, S3a;
    float C0b, S0b, C1b, S1b, C2b, S2b, C3b, S3b;
    __sincosf(xa.x * PI_F, &S0a, &C0a);
    __sincosf(xa.y * PI_F, &S1a, &C1a);
    __sincosf(xa.z * PI_F, &S2a, &C2a);
    __sincosf(xa.w * PI_F, &S3a, &C3a);
    __sincosf(xb.x * PI_F, &S0b, &C0b);
    __sincosf(xb.y * PI_F, &S1b, &C1b);
    __sincosf(xb.z * PI_F, &S2b, &C2b);
    __sincosf(xb.w * PI_F, &S3b, &C3b);

    // packed per-qubit (sampleA, sampleB) pairs
    unsigned long long onep, C0p, S0p, C1p, S1p, C2p, S2p, C3p, S3p;
    PACKX2(onep, 1.0f, 1.0f);
    PACKX2(C0p, C0a, C0b);  PACKX2(S0p, S0a, S0b);
    PACKX2(C1p, C1a, C1b);  PACKX2(S1p, S1a, S1b);
    PACKX2(C2p, C2a, C2b);  PACKX2(S2p, S2a, S2b);
    PACKX2(C3p, C3a, C3b);  PACKX2(S3p, S3a, S3b);

    // r01p[k] = r0[i0]*r1[i1], k = i0*3+i1;  r = (1, C, S)
    unsigned long long r01p[9], r23p[9];
    r01p[0] = onep;  r01p[1] = C1p;  r01p[2] = S1p;
    r01p[3] = C0p;   MULX2(r01p[4], C0p, C1p);  MULX2(r01p[5], C0p, S1p);
    r01p[6] = S0p;   MULX2(r01p[7], S0p, C1p);  MULX2(r01p[8], S0p, S1p);
    r23p[0] = onep;  r23p[1] = C3p;  r23p[2] = S3p;
    r23p[3] = C2p;   MULX2(r23p[4], C2p, C3p);  MULX2(r23p[5], C2p, S3p);
    r23p[6] = S2p;   MULX2(r23p[7], S2p, C3p);  MULX2(r23p[8], S2p, S3p);

    unsigned long long acc0 = 0ull, acc1 = 0ull, acc2 = 0ull, acc3 = 0ull;
#pragma unroll
    for (int k = 0; k < 9; ++k) {
#pragma unroll
        for (int l = 0; l < 9; ++l) {
            unsigned long long mp;
            MULX2(mp, r01p[k], r23p[l]);
            float4 T = Ts[k * 9 + l];
            unsigned long long t0, t1, t2, t3;
            PACKX2(t0, T.x, T.x);
            PACKX2(t1, T.y, T.y);
            PACKX2(t2, T.z, T.z);
            PACKX2(t3, T.w, T.w);
            FMAX2(acc0, t0, mp, acc0);
            FMAX2(acc1, t1, mp, acc1);
            FMAX2(acc2, t2, mp, acc2);
            FMAX2(acc3, t3, mp, acc3);
        }
    }

    float zA0, zB0, zA1, zB1, zA2, zB2, zA3, zB3;
    UNPACKX2(zA0, zB0, acc0);
    UNPACKX2(zA1, zB1, acc1);
    UNPACKX2(zA2, zB2, acc2);
    UNPACKX2(zA3, zB3, acc3);

    out[t]         = make_float4(zA0, zA1, zA2, zA3);
    out[t + halfB] = make_float4(zB0, zB1, zB2, zB3);
}

extern "C" void kernel_launch(void* const* d_in, const int* in_sizes, int n_in,
                              void* d_out, int out_size) {
    const float* x = (const float*)d_in[0];       // [B,4]
    const float* w = (const float*)d_in[1];       // [2,4,2]
    float* out = (float*)d_out;                   // [B,4]
    int B = in_sizes[0] / 4;
    int halfB = B / 2;

    qc_prep_kernel<<<1, 128>>>(w);
    int blocks = (halfB + 255) / 256;
    qc_main_kernel<<<blocks, 256>>>((const float4*)x, (float4*)out, halfB);
}

// round 3
// speedup vs baseline: 3.2429x; 3.2429x over previous
#include <cuda_runtime.h>

// 4-qubit depth-2 variational circuit, B=2^20 samples.
//
// z_w = psi^T A_w psi with A_w = Re(U^H Z_w U), psi a real rank-1 product
// state. Per qubit v[b]v[b'] spans {1, cos(x pi), sin(x pi)} (scaled 1/2), so
//   z_w = sum_{k,l<9} T_w[k,l] * r01[k] * r23[l]
// with r01 = outer((1,C0,S0),(1,C1,S1)), r23 = outer((1,C2,S2),(1,C3,S3)).
// T (81 x 4 floats) is batch-independent -> prep kernel (fully register-
// resident gate evolution + sparse 16-term basis change).
// Main kernel: 2 samples/thread, two-stage contraction, fma.rn.f32x2.

__device__ float4 g_T4[81];

// ---------------- packed f32x2 helpers ----------------
#define PACKX2(d, lo, hi) \
    asm("mov.b64 %0, {%1, %2};" : "=l"(d) : "f"(lo), "f"(hi))
#define UNPACKX2(lo, hi, s) \
    asm("mov.b64 {%0, %1}, %2;" : "=f"(lo), "=f"(hi) : "l"(s))
#define MULX2(d, a, b) \
    asm("mul.rn.f32x2 %0, %1, %2;" : "=l"(d) : "l"(a), "l"(b))
#define FMAX2(d, a, b, c) \
    asm("fma.rn.f32x2 %0, %1, %2, %3;" : "=l"(d) : "l"(a), "l"(b), "l"(c))

// ---------------- prep: build T4 from weights ----------------
__global__ void __launch_bounds__(512) qc_prep_kernel(const float* __restrict__ w) {
    __shared__ float sUr[16][16], sUi[16][16];   // U[s][j]
    __shared__ float sA[4][16][16];              // A_w[j][jp]
    int tid = threadIdx.x;

    // Stage 1: 16 threads each evolve one basis column |j>. All indices
    // compile-time (full unroll, constant masks) -> pure register arrays.
    if (tid < 16) {
        const int j = tid;
        float wv[16];
#pragma unroll
        for (int i = 0; i < 16; ++i) wv[i] = w[i];
        float re[16], im[16];
#pragma unroll
        for (int s = 0; s < 16; ++s) { re[s] = (s == j) ? 1.0f : 0.0f; im[s] = 0.0f; }
#pragma unroll
        for (int d = 0; d < 2; ++d) {
            // CNOT ring: ctrl g -> targ (g+1)%4
#pragma unroll
            for (int g = 0; g < 4; ++g) {
                const int cm = 8 >> g;
                const int tm = 8 >> ((g + 1) & 3);
                float tre[16], tim[16];
#pragma unroll
                for (int s = 0; s < 16; ++s) {
                    const int src = (s & cm) ? (s ^ tm) : s;
                    tre[s] = re[src]; tim[s] = im[src];
                }
#pragma unroll
                for (int s = 0; s < 16; ++s) { re[s] = tre[s]; im[s] = tim[s]; }
            }
#pragma unroll
            for (int q = 0; q < 4; ++q) {
                const int m = 8 >> q;
                float cy, sy; sincosf(0.5f * wv[d * 8 + q * 2 + 0], &sy, &cy);
#pragma unroll
                for (int s = 0; s < 16; ++s) {
                    if (s & m) continue;
                    const int s1 = s | m;
                    float r0 = re[s], i0 = im[s], r1 = re[s1], i1 = im[s1];
                    re[s]  = cy * r0 - sy * r1;  im[s]  = cy * i0 - sy * i1;
                    re[s1] = sy * r0 + cy * r1;  im[s1] = sy * i0 + cy * i1;
                }
                float cp, sp; sincosf(0.5f * wv[d * 8 + q * 2 + 1], &sp, &cp);
#pragma unroll
                for (int s = 0; s < 16; ++s) {
                    float r = re[s], i = im[s];
                    if (s & m) { re[s] = r * cp - i * sp;  im[s] = i * cp + r * sp; }
                    else       { re[s] = r * cp + i * sp;  im[s] = i * cp - r * sp; }
                }
            }
        }
#pragma unroll
        for (int s = 0; s < 16; ++s) { sUr[s][j] = re[s]; sUi[s][j] = im[s]; }
    }
    __syncthreads();

    // Stage 2: A_w[j][jp] = sum_s sign_w(s)*(Ur[s][j]Ur[s][jp]+Ui[s][j]Ui[s][jp])
    for (int e = tid; e < 1024; e += 512) {
        int wq = e >> 8;
        int j  = (e >> 4) & 15;
        int jp = e & 15;
        int mask = 8 >> wq;
        float acc = 0.f;
#pragma unroll
        for (int s = 0; s < 16; ++s) {
            float v = sUr[s][j] * sUr[s][jp] + sUi[s][j] * sUi[s][jp];
            acc += (s & mask) ? -v : v;
        }
        sA[wq][j][jp] = acc;
    }
    __syncthreads();

    // Stage 3: basis change A -> T. For a given (k,l) only 2^4 = 16 of the
    // 256 (j,jp) pairs are nonzero: per qubit q with basis index i_q, the two
    // options o in {0,1} give (b,bp) = (o, o^(i_q==2)), sign flip iff
    // (i_q==1 && o). One thread per (wire, k, l) = 324 threads.
    if (tid < 324) {
        int wq = tid / 81;
        int kl = tid - wq * 81;
        int k = kl / 9, l = kl % 9;
        int i0 = k / 3, i1 = k % 3, i2 = l / 3, i3 = l % 3;
        int x0 = (i0 == 2), x1 = (i1 == 2), x2 = (i2 == 2), x3 = (i3 == 2);
        int n0 = (i0 == 1), n1 = (i1 == 1), n2 = (i2 == 1), n3 = (i3 == 1);
        float acc = 0.f;
#pragma unroll
        for (int c = 0; c < 16; ++c) {
            int o0 = (c >> 3) & 1, o1 = (c >> 2) & 1, o2 = (c >> 1) & 1, o3 = c & 1;
            int j  = (o0 << 3) | (o1 << 2) | (o2 << 1) | o3;
            int jp = ((o0 ^ x0) << 3) | ((o1 ^ x1) << 2) | ((o2 ^ x2) << 1) | (o3 ^ x3);
            int neg = (n0 & o0) ^ (n1 & o1) ^ (n2 & o2) ^ (n3 & o3);
            float v = sA[wq][j][jp];
            acc += neg ? -v : v;
        }
        ((float*)g_T4)[kl * 4 + wq] = acc * (1.0f / 16.0f);
    }
}

// ---------------- main: 2 samples per thread, f32x2 packed ----------------
__global__ void __launch_bounds__(256) qc_main_kernel(
    const float4* __restrict__ x, float4* __restrict__ out, int halfB) {
    __shared__ float4 Ts[81];
    int tid = threadIdx.x;
    if (tid < 81) Ts[tid] = g_T4[tid];
    __syncthreads();

    int t = blockIdx.x * 256 + tid;
    if (t >= halfB) return;

    const float PI_F = 3.14159265358979323846f;
    float4 xa = x[t];
    float4 xb = x[t + halfB];

    float C0a, S0a, C1a, S1a, C2a, S2a, C3a, S3a;
    float C0b, S0b, C1b, S1b, C2b, S2b, C3b, S3b;
    __sincosf(xa.x * PI_F, &S0a, &C0a);
    __sincosf(xa.y * PI_F, &S1a, &C1a);
    __sincosf(xa.z * PI_F, &S2a, &C2a);
    __sincosf(xa.w * PI_F, &S3a, &C3a);
    __sincosf(xb.x * PI_F, &S0b, &C0b);
    __sincosf(xb.y * PI_F, &S1b, &C1b);
    __sincosf(xb.z * PI_F, &S2b, &C2b);
    __sincosf(xb.w * PI_F, &S3b, &C3b);

    unsigned long long onep, C0p, S0p, C1p, S1p, C2p, S2p, C3p, S3p;
    PACKX2(onep, 1.0f, 1.0f);
    PACKX2(C0p, C0a, C0b);  PACKX2(S0p, S0a, S0b);
    PACKX2(C1p, C1a, C1b);  PACKX2(S1p, S1a, S1b);
    PACKX2(C2p, C2a, C2b);  PACKX2(S2p, S2a, S2b);
    PACKX2(C3p, C3a, C3b);  PACKX2(S3p, S3a, S3b);

    unsigned long long r01p[9], r23p[9];
    r01p[0] = onep;  r01p[1] = C1p;  r01p[2] = S1p;
    r01p[3] = C0p;   MULX2(r01p[4], C0p, C1p);  MULX2(r01p[5], C0p, S1p);
    r01p[6] = S0p;   MULX2(r01p[7], S0p, C1p);  MULX2(r01p[8], S0p, S1p);
    r23p[0] = onep;  r23p[1] = C3p;  r23p[2] = S3p;
    r23p[3] = C2p;   MULX2(r23p[4], C2p, C3p);  MULX2(r23p[5], C2p, S3p);
    r23p[6] = S2p;   MULX2(r23p[7], S2p, C3p);  MULX2(r23p[8], S2p, S3p);

    // Two-stage: z_w = sum_k r01[k] * (sum_l T_w[k,l] * r23[l])
    unsigned long long acc0 = 0ull, acc1 = 0ull, acc2 = 0ull, acc3 = 0ull;
#pragma unroll
    for (int k = 0; k < 9; ++k) {
        unsigned long long s0 = 0ull, s1 = 0ull, s2 = 0ull, s3 = 0ull;
#pragma unroll
        for (int l = 0; l < 9; ++l) {
            float4 T = Ts[k * 9 + l];
            unsigned long long t0, t1, t2, t3;
            PACKX2(t0, T.x, T.x);
            PACKX2(t1, T.y, T.y);
            PACKX2(t2, T.z, T.z);
            PACKX2(t3, T.w, T.w);
            FMAX2(s0, t0, r23p[l], s0);
            FMAX2(s1, t1, r23p[l], s1);
            FMAX2(s2, t2, r23p[l], s2);
            FMAX2(s3, t3, r23p[l], s3);
        }
        FMAX2(acc0, r01p[k], s0, acc0);
        FMAX2(acc1, r01p[k], s1, acc1);
        FMAX2(acc2, r01p[k], s2, acc2);
        FMAX2(acc3, r01p[k], s3, acc3);
    }

    float zA0, zB0, zA1, zB1, zA2, zB2, zA3, zB3;
    UNPACKX2(zA0, zB0, acc0);
    UNPACKX2(zA1, zB1, acc1);
    UNPACKX2(zA2, zB2, acc2);
    UNPACKX2(zA3, zB3, acc3);

    out[t]         = make_float4(zA0, zA1, zA2, zA3);
    out[t + halfB] = make_float4(zB0, zB1, zB2, zB3);
}

extern "C" void kernel_launch(void* const* d_in, const int* in_sizes, int n_in,
                              void* d_out, int out_size) {
    const float* x = (const float*)d_in[0];       // [B,4]
    const float* w = (const float*)d_in[1];       // [2,4,2]
    float* out = (float*)d_out;                   // [B,4]
    int B = in_sizes[0] / 4;
    int halfB = B / 2;

    qc_prep_kernel<<<1, 512>>>(w);
    int blocks = (halfB + 255) / 256;
    qc_main_kernel<<<blocks, 256>>>((const float4*)x, (float4*)out, halfB);
}